// round 2
// baseline (speedup 1.0000x reference)
#include <cuda_runtime.h>
#include <mma.h>

using namespace nvcuda;

// Problem constants
#define TT 512
#define BB 64
#define II 1024
#define HH 1024
#define G4 4096           // 4*H
#define BH (BB*HH)        // 65536
#define OUT_SEQ ((size_t)TT*BB*HH)   // 33554432

// ---------------- scratch (device globals; no allocation allowed) ----------
__device__ float g_Wc1[(size_t)G4*II];        // permuted W_ih layer0 [4H,I]
__device__ float g_Whh1[(size_t)G4*HH];       // permuted W_hh layer0
__device__ float g_W2[(size_t)G4*2048];       // permuted [W_ih1 | W_hh1] layer1 [4H,2048]
__device__ float g_b1[G4];
__device__ float g_b2[G4];
__device__ float g_GX1[(size_t)TT*BB*G4];     // 536MB precomputed input proj layer0
__device__ float g_H1[(size_t)TT*BH];         // layer0 outputs (layer1 inputs)
__device__ float g_H2[2][BH];                 // layer1 h ping-pong
__device__ float g_C1[BH];
__device__ float g_C2[BH];

__device__ __forceinline__ float sigmoidf_(float x) { return 1.0f / (1.0f + expf(-x)); }

// ---------------- weight permutation: row 4u+g <- row g*H+u --------------
__global__ void prep_kernel(const float* __restrict__ Wih, const float* __restrict__ Whh,
                            const float* __restrict__ bias) {
    size_t i = (size_t)blockIdx.x * blockDim.x + threadIdx.x;
    if (i >= (size_t)G4 * 2048) return;
    int r = (int)(i >> 11);
    int k = (int)(i & 2047);
    int u = r >> 2, g = r & 3;
    int src = (g << 10) | u;             // g*H + u
    // layer 1 combined [Wih1 | Whh1]
    const size_t l1 = (size_t)G4 * II;   // layer offset in Wih/Whh
    float v = (k < 1024) ? Wih[l1 + (size_t)src * II + k]
                         : Whh[l1 + (size_t)src * HH + (k - 1024)];
    g_W2[(size_t)r * 2048 + k] = v;
    if (k < 1024) {
        g_Wc1[(size_t)r * II + k]  = Wih[(size_t)src * II + k];
        g_Whh1[(size_t)r * HH + k] = Whh[(size_t)src * HH + k];
    }
    if (k == 0) {
        g_b1[r] = bias[src];
        g_b2[r] = bias[G4 + src];
    }
}

__global__ void init_c_kernel(const float* __restrict__ c0) {
    int i = blockIdx.x * blockDim.x + threadIdx.x;
    if (i < BH) { g_C1[i] = c0[i]; g_C2[i] = c0[BH + i]; }
}

// ---------------- wmma tile helper: acc[0..1] += A[16,K] * W[32,K]^T -----
__device__ __forceinline__ void mm_acc(
    wmma::fragment<wmma::accumulator, 16, 16, 8, float>* acc,
    const float* __restrict__ A, int lda,
    const float* __restrict__ W, int ldw, int K)
{
    wmma::fragment<wmma::matrix_a, 16, 16, 8, wmma::precision::tf32, wmma::row_major> a;
    wmma::fragment<wmma::matrix_b, 16, 16, 8, wmma::precision::tf32, wmma::col_major> b0, b1;
#pragma unroll 4
    for (int k = 0; k < K; k += 8) {
        wmma::load_matrix_sync(a, A + k, lda);
#pragma unroll
        for (int i = 0; i < a.num_elements; i++) a.x[i] = wmma::__float_to_tf32(a.x[i]);
        wmma::load_matrix_sync(b0, W + k, ldw);
        wmma::load_matrix_sync(b1, W + (size_t)16 * ldw + k, ldw);
#pragma unroll
        for (int i = 0; i < b0.num_elements; i++) {
            b0.x[i] = wmma::__float_to_tf32(b0.x[i]);
            b1.x[i] = wmma::__float_to_tf32(b1.x[i]);
        }
        wmma::mma_sync(acc[0], a, b0, acc[0]);
        wmma::mma_sync(acc[1], a, b1, acc[1]);
    }
}

// ---------------- precompute GX1 = x @ Wc1^T + b1  -----------------------
// grid: (N/64=64, M/64=512), 256 threads (8 warps, each 16x32)
__global__ void gx_kernel(const float* __restrict__ x) {
    __shared__ float sm[64 * 64];
    int n0 = blockIdx.x * 64;
    int row0 = blockIdx.y * 64;
    int warp = threadIdx.x >> 5;
    int wm = warp >> 1, wn = warp & 1;

    wmma::fragment<wmma::accumulator, 16, 16, 8, float> acc[2];
    wmma::fill_fragment(acc[0], 0.0f);
    wmma::fill_fragment(acc[1], 0.0f);

    const float* A = x + (size_t)(row0 + wm * 16) * II;
    const float* W = g_Wc1 + (size_t)(n0 + wn * 32) * II;
    mm_acc(acc, A, II, W, II, II);

    wmma::store_matrix_sync(&sm[(wm * 16) * 64 + wn * 32], acc[0], 64, wmma::mem_row_major);
    wmma::store_matrix_sync(&sm[(wm * 16) * 64 + wn * 32 + 16], acc[1], 64, wmma::mem_row_major);
    __syncthreads();

#pragma unroll
    for (int i = 0; i < 16; i++) {
        int e = threadIdx.x + i * 256;
        int row = e >> 6, col = e & 63;
        g_GX1[((size_t)row0 + row) * G4 + n0 + col] = sm[row * 64 + col] + g_b1[n0 + col];
    }
}

// ---------------- fused step kernel --------------------------------------
// launch t in [0,512]: blocks 0..63 do layer0 step t (if t<512),
//                      blocks 64..127 do layer1 step t-1 (if t>=1)
__global__ void step_kernel(const float* __restrict__ h0, float* __restrict__ out, int t) {
    __shared__ float sm[64 * 64];
    int bid = blockIdx.x;
    int layer = bid >> 6;
    int n0 = (bid & 63) << 6;
    int warp = threadIdx.x >> 5;
    int wm = warp >> 1, wn = warp & 1;

    wmma::fragment<wmma::accumulator, 16, 16, 8, float> acc[2];
    wmma::fill_fragment(acc[0], 0.0f);
    wmma::fill_fragment(acc[1], 0.0f);

    if (layer == 0) {
        if (t >= TT) return;
        const float* hprev = (t == 0) ? h0 : (g_H1 + (size_t)(t - 1) * BH);
        const float* A = hprev + (size_t)(wm * 16) * HH;
        const float* W = g_Whh1 + (size_t)(n0 + wn * 32) * HH;
        mm_acc(acc, A, HH, W, HH, HH);

        wmma::store_matrix_sync(&sm[(wm * 16) * 64 + wn * 32], acc[0], 64, wmma::mem_row_major);
        wmma::store_matrix_sync(&sm[(wm * 16) * 64 + wn * 32 + 16], acc[1], 64, wmma::mem_row_major);
        __syncthreads();

#pragma unroll
        for (int i = 0; i < 4; i++) {
            int e = threadIdx.x + i * 256;       // 0..1023
            int row = e >> 4, u = e & 15;
            const float* gx = g_GX1 + ((size_t)t * BB + row) * G4 + n0 + 4 * u;
            float gi = sm[row * 64 + 4 * u + 0] + gx[0];
            float gf = sm[row * 64 + 4 * u + 1] + gx[1];
            float gg = sm[row * 64 + 4 * u + 2] + gx[2];
            float go = sm[row * 64 + 4 * u + 3] + gx[3];
            float iv = sigmoidf_(gi), fv = sigmoidf_(gf);
            float gv = tanhf(gg),     ov = sigmoidf_(go);
            int j = (n0 >> 2) + u;                // global unit 0..1023
            float c_old = g_C1[row * HH + j];
            float c_new = fv * c_old + iv * gv;
            g_C1[row * HH + j] = c_new;
            g_H1[(size_t)t * BH + row * HH + j] = ov * tanhf(c_new);
        }
    } else {
        if (t < 1) return;
        int s = t - 1;
        const float* A1 = g_H1 + (size_t)s * BH + (size_t)(wm * 16) * HH;
        const float* h2prev = (s == 0) ? (h0 + BH) : g_H2[(s - 1) & 1];
        const float* A2 = h2prev + (size_t)(wm * 16) * HH;
        const float* Wb = g_W2 + (size_t)(n0 + wn * 32) * 2048;
        mm_acc(acc, A1, HH, Wb, 2048, 1024);          // input-proj part
        mm_acc(acc, A2, HH, Wb + 1024, 2048, 1024);   // recurrent part

        wmma::store_matrix_sync(&sm[(wm * 16) * 64 + wn * 32], acc[0], 64, wmma::mem_row_major);
        wmma::store_matrix_sync(&sm[(wm * 16) * 64 + wn * 32 + 16], acc[1], 64, wmma::mem_row_major);
        __syncthreads();

        float* h2cur = g_H2[s & 1];
#pragma unroll
        for (int i = 0; i < 4; i++) {
            int e = threadIdx.x + i * 256;
            int row = e >> 4, u = e & 15;
            float gi = sm[row * 64 + 4 * u + 0] + g_b2[n0 + 4 * u + 0];
            float gf = sm[row * 64 + 4 * u + 1] + g_b2[n0 + 4 * u + 1];
            float gg = sm[row * 64 + 4 * u + 2] + g_b2[n0 + 4 * u + 2];
            float go = sm[row * 64 + 4 * u + 3] + g_b2[n0 + 4 * u + 3];
            float iv = sigmoidf_(gi), fv = sigmoidf_(gf);
            float gv = tanhf(gg),     ov = sigmoidf_(go);
            int j = (n0 >> 2) + u;
            float c_old = g_C2[row * HH + j];
            float c_new = fv * c_old + iv * gv;
            g_C2[row * HH + j] = c_new;
            float hv = ov * tanhf(c_new);
            h2cur[row * HH + j] = hv;
            out[(size_t)s * BH + row * HH + j] = hv;
        }
    }
}

// ---------------- final h_n / c_n copy -----------------------------------
__global__ void final_kernel(float* __restrict__ out) {
    int i = blockIdx.x * blockDim.x + threadIdx.x;
    if (i >= BH) return;
    out[OUT_SEQ + i]           = g_H1[(size_t)(TT - 1) * BH + i];  // h_n layer0
    out[OUT_SEQ + BH + i]      = g_H2[(TT - 1) & 1][i];            // h_n layer1
    out[OUT_SEQ + 2 * BH + i]  = g_C1[i];                          // c_n layer0
    out[OUT_SEQ + 3 * BH + i]  = g_C2[i];                          // c_n layer1
}

extern "C" void kernel_launch(void* const* d_in, const int* in_sizes, int n_in,
                              void* d_out, int out_size) {
    const float* x   = (const float*)d_in[0];
    const float* Wih = (const float*)d_in[1];
    const float* Whh = (const float*)d_in[2];
    const float* b   = (const float*)d_in[3];
    const float* h0  = (const float*)d_in[4];
    const float* c0  = (const float*)d_in[5];
    float* out = (float*)d_out;

    prep_kernel<<<8192, 1024>>>(Wih, Whh, b);
    init_c_kernel<<<64, 1024>>>(c0);
    gx_kernel<<<dim3(64, 512), 256>>>(x);
    for (int t = 0; t <= TT; t++) {
        step_kernel<<<128, 256>>>(h0, out, t);
    }
    final_kernel<<<64, 1024>>>(out);
}

// round 3
// speedup vs baseline: 10.2066x; 10.2066x over previous
#include <cuda_runtime.h>
#include <cuda_fp16.h>
#include <mma.h>
using namespace nvcuda;

#define TT 512
#define BB 64
#define II 1024
#define HH 1024
#define G4 4096
#define BH (BB*HH)
#define OUT_SEQ ((size_t)TT*BB*HH)

#define KT 64                         // k-tile in halves
#define NS 4                          // pipeline stages
#define AROW 72                       // padded halves per smem row
#define STAGE_BYTES (2*64*AROW*2)     // A(64 rows)+W(64 rows) = 18432 B
#define SMEM_BYTES (NS*STAGE_BYTES)   // 73728 B

// ---------------- device scratch (no allocation allowed) ------------------
__device__ __half g_Wc1h[(size_t)G4*II];      // permuted W_ih layer0, half
__device__ __half g_Whh1h[(size_t)G4*HH];     // permuted W_hh layer0, half
__device__ __half g_W2h[(size_t)G4*2048];     // permuted [W_ih1|W_hh1] layer1, half
__device__ float  g_b1[G4], g_b2[G4];
__device__ __half g_Xh[(size_t)TT*BB*II];     // x in half
__device__ float  g_GX1[(size_t)TT*BB*G4];    // precomputed input proj layer0 (fp32)
__device__ __half g_H1[(size_t)TT*BH];        // layer0 h outputs (half, GEMM input)
__device__ __half g_H2[2][BH];                // layer1 h ping-pong (half)
__device__ __half g_H0h[2][BH];               // h0 converted to half
__device__ float  g_C1[BH], g_C2[BH];

__device__ __forceinline__ float sigmoidf_(float x){ return 1.f/(1.f+expf(-x)); }

__device__ __forceinline__ void cp16(void* dst, const void* src){
    unsigned s = (unsigned)__cvta_generic_to_shared(dst);
    asm volatile("cp.async.ca.shared.global [%0], [%1], 16;\n" :: "r"(s), "l"(src));
}

// Load one k-tile stage: A 64x64 halves + W 64x64 halves, 4 chunks/thread
__device__ __forceinline__ void load_stage(char* st, const __half* A0, const __half* A1,
        int split, int lda, const __half* W, int ldw, int k0, int tid)
{
    const __half* Ap = A0; int kc = k0;
    if (split && k0 >= split){ Ap = A1; kc = k0 - split; }
#pragma unroll
    for (int j = 0; j < 4; j++){
        int c = tid + j*256;
        int row = (c & 511) >> 3;
        int cc  = c & 7;
        if (c < 512)
            cp16(st + row*(AROW*2) + cc*16, Ap + (size_t)row*lda + kc + cc*8);
        else
            cp16(st + 64*AROW*2 + row*(AROW*2) + cc*16, W + (size_t)row*ldw + k0 + cc*8);
    }
}

// C[64x64] = A[64xK] * W[64xK]^T  (A optionally split at 'split' between A0/A1)
// Result left in (float*)smem, row-major ld=64. 256 threads / 8 warps.
__device__ __forceinline__ void gemm64x64(char* smem,
    const __half* A0, const __half* A1, int split, int lda,
    const __half* W, int ldw, int K)
{
    int tid = threadIdx.x;
    int warp = tid >> 5;
    int wm = warp >> 1, wn = warp & 1;

    wmma::fragment<wmma::accumulator,16,16,16,float> acc[2];
    wmma::fill_fragment(acc[0], 0.f);
    wmma::fill_fragment(acc[1], 0.f);

    int ntiles = K / KT;
#pragma unroll
    for (int p = 0; p < NS-1; p++){
        load_stage(smem + p*STAGE_BYTES, A0, A1, split, lda, W, ldw, p*KT, tid);
        asm volatile("cp.async.commit_group;\n");
    }
    for (int t = 0; t < ntiles; t++){
        asm volatile("cp.async.wait_group 2;\n");
        __syncthreads();
        int pf = t + NS - 1;
        if (pf < ntiles)
            load_stage(smem + (pf & (NS-1))*STAGE_BYTES, A0, A1, split, lda, W, ldw, pf*KT, tid);
        asm volatile("cp.async.commit_group;\n");

        const __half* As = (const __half*)(smem + (t & (NS-1))*STAGE_BYTES);
        const __half* Ws = As + 64*AROW;
#pragma unroll
        for (int ks = 0; ks < KT/16; ks++){
            wmma::fragment<wmma::matrix_a,16,16,16,__half,wmma::row_major> a;
            wmma::fragment<wmma::matrix_b,16,16,16,__half,wmma::col_major> b;
            wmma::load_matrix_sync(a, As + (wm*16)*AROW + ks*16, AROW);
            wmma::load_matrix_sync(b, Ws + (wn*32)*AROW + ks*16, AROW);
            wmma::mma_sync(acc[0], a, b, acc[0]);
            wmma::load_matrix_sync(b, Ws + (wn*32+16)*AROW + ks*16, AROW);
            wmma::mma_sync(acc[1], a, b, acc[1]);
        }
    }
    asm volatile("cp.async.wait_group 0;\n");
    __syncthreads();
    float* outsm = (float*)smem;
    wmma::store_matrix_sync(outsm + (wm*16)*64 + wn*32,      acc[0], 64, wmma::mem_row_major);
    wmma::store_matrix_sync(outsm + (wm*16)*64 + wn*32 + 16, acc[1], 64, wmma::mem_row_major);
    __syncthreads();
}

// ---------------- prep: permute weights (row 4u+g <- g*H+u), half-convert --
__global__ void prep_w(const float* __restrict__ Wih, const float* __restrict__ Whh,
                       const float* __restrict__ b){
    size_t i = (size_t)blockIdx.x*blockDim.x + threadIdx.x;
    if (i >= (size_t)G4*2048) return;
    int r = (int)(i >> 11), k = (int)(i & 2047);
    int u = r >> 2, g = r & 3;
    int src = (g << 10) | u;
    const size_t l1 = (size_t)G4*II;
    float v = (k < 1024) ? Wih[l1 + (size_t)src*II + k]
                         : Whh[l1 + (size_t)src*HH + (k-1024)];
    g_W2h[(size_t)r*2048 + k] = __float2half(v);
    if (k < 1024){
        g_Wc1h[(size_t)r*II + k]  = __float2half(Wih[(size_t)src*II + k]);
        g_Whh1h[(size_t)r*HH + k] = __float2half(Whh[(size_t)src*HH + k]);
    }
    if (k == 0){ g_b1[r] = b[src]; g_b2[r] = b[G4+src]; }
}

__global__ void prep_x(const float* __restrict__ x){
    size_t i = (size_t)blockIdx.x*blockDim.x + threadIdx.x;
    size_t n4 = (size_t)TT*BB*II/4;
    if (i >= n4) return;
    float4 v = ((const float4*)x)[i];
    __half2* dst = (__half2*)g_Xh;
    dst[2*i]   = __floats2half2_rn(v.x, v.y);
    dst[2*i+1] = __floats2half2_rn(v.z, v.w);
}

__global__ void init_c(const float* __restrict__ h0, const float* __restrict__ c0){
    int i = blockIdx.x*blockDim.x + threadIdx.x;
    if (i < BH){
        g_C1[i] = c0[i];
        g_C2[i] = c0[BH+i];
        g_H0h[0][i] = __float2half(h0[i]);
        g_H0h[1][i] = __float2half(h0[BH+i]);
    }
}

// ---------------- GX1 = x @ Wc1^T + b1 ------------------------------------
__global__ void gx_kernel(){
    extern __shared__ char smem[];
    int n0   = blockIdx.x * 64;
    int row0 = blockIdx.y * 64;
    gemm64x64(smem, g_Xh + (size_t)row0*II, nullptr, 0, II,
              g_Wc1h + (size_t)n0*II, II, II);
    float* sm = (float*)smem;
    int tid = threadIdx.x;
#pragma unroll
    for (int i = 0; i < 16; i++){
        int e = tid + i*256;
        int row = e >> 6, col = e & 63;
        g_GX1[((size_t)row0 + row)*G4 + n0 + col] = sm[row*64+col] + g_b1[n0+col];
    }
}

// ---------------- fused step: blocks 0..63 layer0(t), 64..127 layer1(t-1) --
__global__ void step_kernel(float* __restrict__ out, int t){
    extern __shared__ char smem[];
    int bid = blockIdx.x;
    int tid = threadIdx.x;

    if (bid < 64){
        if (t >= TT) return;
        int n0 = bid * 64;
        const __half* A = (t == 0) ? g_H0h[0] : (g_H1 + (size_t)(t-1)*BH);
        gemm64x64(smem, A, nullptr, 0, HH, g_Whh1h + (size_t)n0*HH, HH, HH);
        float* sm = (float*)smem;
#pragma unroll
        for (int i = 0; i < 4; i++){
            int e = tid + i*256;
            int row = e >> 4, u = e & 15;
            const float* gx = g_GX1 + ((size_t)t*BB + row)*G4 + n0 + 4*u;
            float gi = sm[row*64+4*u+0] + gx[0];
            float gf = sm[row*64+4*u+1] + gx[1];
            float gg = sm[row*64+4*u+2] + gx[2];
            float go = sm[row*64+4*u+3] + gx[3];
            float iv = sigmoidf_(gi), fv = sigmoidf_(gf);
            float gv = tanhf(gg),     ov = sigmoidf_(go);
            int j = (n0 >> 2) + u;
            float c = fv * g_C1[row*HH+j] + iv * gv;
            g_C1[row*HH+j] = c;
            float hv = ov * tanhf(c);
            g_H1[(size_t)t*BH + row*HH + j] = __float2half(hv);
            if (t == TT-1) out[OUT_SEQ + row*HH + j] = hv;   // h_n layer0 fp32
        }
    } else {
        if (t < 1) return;
        int s = t - 1;
        int n0 = (bid - 64) * 64;
        const __half* A0 = g_H1 + (size_t)s*BH;
        const __half* A1 = (s == 0) ? g_H0h[1] : g_H2[(s-1)&1];
        gemm64x64(smem, A0, A1, 1024, HH, g_W2h + (size_t)n0*2048, 2048, 2048);
        float* sm = (float*)smem;
        __half* h2 = g_H2[s&1];
#pragma unroll
        for (int i = 0; i < 4; i++){
            int e = tid + i*256;
            int row = e >> 4, u = e & 15;
            float gi = sm[row*64+4*u+0] + g_b2[n0+4*u+0];
            float gf = sm[row*64+4*u+1] + g_b2[n0+4*u+1];
            float gg = sm[row*64+4*u+2] + g_b2[n0+4*u+2];
            float go = sm[row*64+4*u+3] + g_b2[n0+4*u+3];
            float iv = sigmoidf_(gi), fv = sigmoidf_(gf);
            float gv = tanhf(gg),     ov = sigmoidf_(go);
            int j = (n0 >> 2) + u;
            float c = fv * g_C2[row*HH+j] + iv * gv;
            g_C2[row*HH+j] = c;
            float hv = ov * tanhf(c);
            h2[row*HH+j] = __float2half(hv);
            out[(size_t)s*BH + row*HH + j] = hv;             // output seq fp32
        }
    }
}

// ---------------- final h_n / c_n -----------------------------------------
__global__ void final_k(float* __restrict__ out){
    int i = blockIdx.x*blockDim.x + threadIdx.x;
    if (i >= BH) return;
    out[OUT_SEQ + BH + i]   = out[(size_t)(TT-1)*BH + i];   // h_n layer1
    out[OUT_SEQ + 2*BH + i] = g_C1[i];                      // c_n layer0
    out[OUT_SEQ + 3*BH + i] = g_C2[i];                      // c_n layer1
}

extern "C" void kernel_launch(void* const* d_in, const int* in_sizes, int n_in,
                              void* d_out, int out_size){
    const float* x   = (const float*)d_in[0];
    const float* Wih = (const float*)d_in[1];
    const float* Whh = (const float*)d_in[2];
    const float* b   = (const float*)d_in[3];
    const float* h0  = (const float*)d_in[4];
    const float* c0  = (const float*)d_in[5];
    float* out = (float*)d_out;

    cudaFuncSetAttribute(gx_kernel,  cudaFuncAttributeMaxDynamicSharedMemorySize, SMEM_BYTES);
    cudaFuncSetAttribute(step_kernel, cudaFuncAttributeMaxDynamicSharedMemorySize, SMEM_BYTES);

    prep_w<<<(G4*2048 + 255)/256, 256>>>(Wih, Whh, b);
    prep_x<<<((TT*BB*II/4) + 255)/256, 256>>>(x);
    init_c<<<64, 1024>>>(h0, c0);
    gx_kernel<<<dim3(64, 512), 256, SMEM_BYTES>>>();
    for (int t = 0; t <= TT; t++)
        step_kernel<<<128, 256, SMEM_BYTES>>>(out, t);
    final_k<<<64, 1024>>>(out);
}